// round 8
// baseline (speedup 1.0000x reference)
#include <cuda_runtime.h>

#define NBB 256                 // buckets for 16384-pt sets
#define NBA 64                  // buckets for 1024-pt sets
#define XLOW  (-4.5f)
#define BWB   (9.0f / 256.0f)
#define BWA   (9.0f / 64.0f)
#define INVB  (256.0f / 9.0f)
#define INVA  (64.0f / 9.0f)

// scratch (device globals; no allocation)
__device__ float4 g_Bs[24][16384];   // binned gt/tgt: {x,y,z, 0.5*|p|^2}
__device__ float4 g_As[24][1024];    // binned sp/tsp
__device__ int    g_Boff[24][NBB + 1];
__device__ int    g_Aoff[24][NBA + 1];
__device__ float  g_acc[4];          // [0]=p1 ch1, [1]=p1 ch2, [2]=p2 ch1, [3]=p2 ch2

__device__ __forceinline__ int bkt(float x, float invw, int nb) {
    int b = (int)((x - XLOW) * invw);
    return min(max(b, 0), nb - 1);
}
__device__ __forceinline__ float wmaxf(float v) {   // v >= 0 (or +inf)
    return __int_as_float(__reduce_max_sync(0xffffffffu, __float_as_int(v)));
}

// ---------------- binning: counting sort into fixed x-bins. 48 blocks.
__global__ __launch_bounds__(1024)
void k_bin(const float* __restrict__ gt, const float* __restrict__ sp,
           const float* __restrict__ tgt, const float* __restrict__ tsp)
{
    __shared__ int hist[256], scan[256], cursor[256];
    const int job = blockIdx.x;
    const int tid = threadIdx.x;

    int n, nb; float invw; const float* src; float4* dst; int* offs;
    if (job < 24) {
        n = 16384; nb = NBB; invw = INVB;
        src = (job < 8) ? gt + (size_t)job * 16384 * 3
                        : tgt + (size_t)(job - 8) * 16384 * 3;
        dst = g_Bs[job]; offs = g_Boff[job];
    } else {
        int j = job - 24;
        n = 1024; nb = NBA; invw = INVA;
        src = (j < 8) ? sp + (size_t)j * 1024 * 3
                      : tsp + (size_t)(j - 8) * 1024 * 3;
        dst = g_As[j]; offs = g_Aoff[j];
    }
    if (job == 0 && tid < 4) g_acc[tid] = 0.0f;

    if (tid < nb) hist[tid] = 0;
    __syncthreads();
    for (int i = tid; i < n; i += 1024)
        atomicAdd(&hist[bkt(src[(size_t)i * 3], invw, nb)], 1);
    __syncthreads();

    int v = (tid < nb) ? hist[tid] : 0;
    if (tid < nb) scan[tid] = v;
    __syncthreads();
    for (int off = 1; off < nb; off <<= 1) {            // Kogge-Stone inclusive
        int t = 0;
        if (tid < nb && tid >= off) t = scan[tid - off];
        __syncthreads();
        if (tid < nb) scan[tid] += t;
        __syncthreads();
    }
    if (tid < nb) {
        int excl = scan[tid] - v;
        cursor[tid] = excl;
        offs[tid] = excl;
    }
    if (tid == 0) offs[nb] = n;
    __syncthreads();

    for (int i = tid; i < n; i += 1024) {
        float x = src[(size_t)i * 3 + 0];
        float y = src[(size_t)i * 3 + 1];
        float z = src[(size_t)i * 3 + 2];
        int b = bkt(x, invw, nb);
        int pos = atomicAdd(&cursor[b], 1);
        dst[pos] = make_float4(x, y, z, 0.5f * (x * x + y * y + z * z));
    }
}

// ---------------- NN: blocks [0,192) = pass1 (A->B, gmem DB), rest = pass2 (B->A, smem DB)
__global__ __launch_bounds__(128)
void k_nn()
{
    __shared__ float4 adb[1024];
    __shared__ int    aoff[NBA + 1];

    const int bx = blockIdx.x;
    const int tid = threadIdx.x, lane = tid & 31, warp = tid >> 5;
    const float INF = __int_as_float(0x7f800000);

    float4 Q; int job, acc_idx, nb; float w, invw;
    const float4* __restrict__ P; const int* __restrict__ O;

    if (bx < 192) {
        job = bx >> 3;
        int qidx = (bx & 7) * 128 + warp * 32 + lane;
        Q = g_As[job][qidx];
        P = g_Bs[job]; O = g_Boff[job];
        nb = NBB; w = BWB; invw = INVB;
        acc_idx = (job < 8) ? 0 : 1;
    } else {
        int b2 = bx - 192;
        job = b2 >> 7;
        const float4* __restrict__ Ap = g_As[job];
        for (int i = tid; i < 1024; i += 128) adb[i] = Ap[i];
        for (int i = tid; i < NBA + 1; i += 128) aoff[i] = g_Aoff[job][i];
        __syncthreads();
        int qidx = (b2 & 127) * 128 + warp * 32 + lane;
        Q = g_Bs[job][qidx];
        P = adb; O = aoff;
        nb = NBA; w = BWA; invw = INVA;
        acc_idx = (job < 8) ? 2 : 3;
    }

    const float qx = Q.x, qy = Q.y, qz = Q.z, hq = Q.w;

    // warp x-range for conservative gap bounds
    float xlo = qx, xhi = qx;
#pragma unroll
    for (int o = 16; o > 0; o >>= 1) {
        xlo = fminf(xlo, __shfl_xor_sync(0xffffffffu, xlo, o));
        xhi = fmaxf(xhi, __shfl_xor_sync(0xffffffffu, xhi, o));
    }
    int b0 = bkt(0.5f * (xlo + xhi), invw, nb);

    float m0 = INF, m1 = INF;
    auto proc = [&](int b) {
        int s = O[b], e = O[b + 1];
        int i = s;
        for (; i + 1 < e; i += 2) {
            float4 p0 = P[i], p1 = P[i + 1];
            float t0 = fmaf(-qx, p0.x, fmaf(-qy, p0.y, fmaf(-qz, p0.z, p0.w)));
            float t1 = fmaf(-qx, p1.x, fmaf(-qy, p1.y, fmaf(-qz, p1.z, p1.w)));
            m0 = fminf(m0, t0);
            m1 = fminf(m1, t1);
        }
        if (i < e) {
            float4 p = P[i];
            m0 = fminf(m0, fmaf(-qx, p.x, fmaf(-qy, p.y, fmaf(-qz, p.z, p.w))));
        }
    };

    proc(b0);
    float Mq = wmaxf(fminf(m0, m1) + hq);

    int tr = b0 + 1, tl = b0 - 1;
    bool canR = (tr < nb), canL = (tl >= 0);
    while (canR || canL) {
        float gR = INF, gL = INF;
        if (canR) {
            gR = fmaxf((XLOW + (float)tr * w) - xhi, 0.0f);
            if (0.5f * gR * gR >= Mq) { canR = false; gR = INF; }
        }
        if (canL) {
            gL = fmaxf(xlo - (XLOW + (float)(tl + 1) * w), 0.0f);
            if (0.5f * gL * gL >= Mq) { canL = false; gL = INF; }
        }
        if (!canR && !canL) break;
        if (canR && (!canL || gR <= gL)) { proc(tr); tr++; canR = (tr < nb); }
        else                             { proc(tl); tl--; canL = (tl >= 0); }
        Mq = wmaxf(fminf(m0, m1) + hq);
    }

    float r = fminf(m0, m1) + hq;          // = min dist^2 / 2 for this query
#pragma unroll
    for (int o = 16; o > 0; o >>= 1) r += __shfl_xor_sync(0xffffffffu, r, o);
    if (lane == 0) atomicAdd(&g_acc[acc_idx], r);
}

// ---------------- finalize: consistency MSE + combine
__global__ __launch_bounds__(1024)
void k_final(const float* __restrict__ sp,
             const float* __restrict__ tsp,
             const float* __restrict__ M,
             float* __restrict__ out)
{
    int tid = threadIdx.x;
    float e = 0.0f;
#pragma unroll
    for (int k = 0; k < 16; k++) {
        int idx = tid + k * 1024;          // [0, 16384) = T*B*S
        int t  = idx >> 13;
        int bs = idx & 8191;
        const float* p = sp + (size_t)bs * 3;
        float x = p[0], y = p[1], z = p[2];
        const float* m = M + t * 9;
        const float* q = tsp + (size_t)idx * 3;
#pragma unroll
        for (int cc = 0; cc < 3; cc++) {
            float v = fmaf(x, m[cc], fmaf(y, m[3 + cc], z * m[6 + cc]));
            float d = v - q[cc];
            e = fmaf(d, d, e);
        }
    }
    __shared__ float sh[1024];
    sh[tid] = e; __syncthreads();
    for (int s = 512; s > 0; s >>= 1) {
        if (tid < s) sh[tid] += sh[tid + s];
        __syncthreads();
    }

    if (tid == 0) {
        float a0 = g_acc[0], a1 = g_acc[1], a2 = g_acc[2], a3 = g_acc[3];
        // sums are dist^2/2; cd = (mean_min1 + mean_min2)/2 = sum1/cnt1 + sum2/cnt2 (half-units)
        float cd1 = a0 / 8192.0f  + a2 / 131072.0f;   // 8*1024, 8*16384
        float cd2 = a1 / 16384.0f + a3 / 262144.0f;   // 16*1024, 16*16384
        float consist = sh[0] * (1000.0f / 49152.0f); // mean over T*B*S*D
        out[0] = (cd1 + cd2) / 3.0f + consist;        // /(T+1)
    }
}

extern "C" void kernel_launch(void* const* d_in, const int* in_sizes, int n_in,
                              void* d_out, int out_size) {
    const float* gt  = (const float*)d_in[0];   // [8,16384,3]
    const float* sp  = (const float*)d_in[1];   // [8,1024,3]
    const float* tgt = (const float*)d_in[2];   // [2,8,16384,3] -> 16 batches
    const float* tsp = (const float*)d_in[3];   // [2,8,1024,3]  -> 16 batches
    const float* M   = (const float*)d_in[4];   // [2,3,3]
    (void)in_sizes; (void)n_in; (void)out_size;

    k_bin  <<<48, 1024>>>(gt, sp, tgt, tsp);
    k_nn   <<<192 + 24 * 128, 128>>>();
    k_final<<<1, 1024>>>(sp, tsp, M, (float*)d_out);
}

// round 9
// speedup vs baseline: 5.6985x; 5.6985x over previous
#include <cuda_runtime.h>

#define SD 1024          // structure points per batch (rows)
#define NP 16384         // gt points per batch (cols)
#define WC 64            // columns per warp
#define WARPS 4
#define COLS_PER_BLOCK (WARPS * WC)   // 256

// scratch (no allocations allowed)
__device__ __align__(16) int g_rowmin[24576]; // 8*1024 (cham1) + 16*1024 (cham2), float bits
__device__ float g_acc[4];                    // [0]=colsum1, [1]=colsum2

__device__ __forceinline__ unsigned long long pack2(float lo, float hi) {
    unsigned long long r;
    asm("mov.b64 %0, {%1, %2};" : "=l"(r) : "f"(lo), "f"(hi));
    return r;
}

// two pairs: q = (nax,nay,naz).(p) + ha + hb (packed f32x2);
// update the two row-mins and one of the 4 local column chains.
__device__ __forceinline__ void pair_step(
    unsigned long long nax2, unsigned long long nay2, unsigned long long naz2,
    unsigned long long ha2,
    unsigned long long px2, unsigned long long py2, unsigned long long pz2,
    unsigned long long hb2,
    float& rlo, float& rhi, float& acc)
{
    asm("{\n\t"
        ".reg .b64 q;\n\t"
        ".reg .f32 lo, hi;\n\t"
        "fma.rn.f32x2 q, %5, %9, %6;\n\t"   // naz2*pz2 + ha2
        "fma.rn.f32x2 q, %4, %8, q;\n\t"    // + nay2*py2
        "fma.rn.f32x2 q, %3, %7, q;\n\t"    // + nax2*px2
        "add.rn.f32x2 q, q, %10;\n\t"       // + hb2
        "mov.b64 {lo, hi}, q;\n\t"
        "min.f32 %0, %0, lo;\n\t"
        "min.f32 %1, %1, hi;\n\t"
        "min.f32 %2, %2, lo;\n\t"
        "min.f32 %2, %2, hi;\n\t"
        "}"
        : "+f"(rlo), "+f"(rhi), "+f"(acc)
        : "l"(nax2), "l"(nay2), "l"(naz2), "l"(ha2),
          "l"(px2), "l"(py2), "l"(pz2), "l"(hb2));
}

__global__ __launch_bounds__(1024)
void k_init() {
    int i = blockIdx.x * 1024 + threadIdx.x;
    g_rowmin[i] = 0x7f800000;
    if (i < 4) g_acc[i] = 0.0f;
}

// merged chamfer: blockIdx.y in [0,24): y<16 -> (tsp,tgt) job, y>=16 -> (sp,gt) job
__global__ __launch_bounds__(WARPS * 32)
void k_chamfer(const float* __restrict__ sp,  const float* __restrict__ gt,
               const float* __restrict__ tsp, const float* __restrict__ tgt)
{
    __shared__ ulonglong2 tile2[WARPS][32][2];   // duplicated packs {xx,yy},{zz,hh}

    const int y    = blockIdx.y;
    const int tid  = threadIdx.x;
    const int lane = tid & 31;
    const int warp = tid >> 5;
    const float INF = __int_as_float(0x7f800000);

    const float* pa; const float* pb; int rowoff, acc_idx;
    if (y < 16) { pa = tsp + (size_t)y * SD * 3;       pb = tgt + (size_t)y * NP * 3;
                  rowoff = 8192 + y * SD;              acc_idx = 1; }
    else        { int b = y - 16;
                  pa = sp + (size_t)b * SD * 3;        pb = gt + (size_t)b * NP * 3;
                  rowoff = b * SD;                     acc_idx = 0; }

    // ---- all 1024 rows of this batch in this warp's registers ----
    // lane l holds rows { i*32 + l }, packed in pairs (2i, 2i+1)
    unsigned long long nax2[16], nay2[16], naz2[16], ha2[16];
    float rl[16], rh[16];
#pragma unroll
    for (int i = 0; i < 16; i++) {
        int r0 = (2 * i) * 32 + lane;
        int r1 = r0 + 32;
        float x0 = pa[r0*3+0], y0 = pa[r0*3+1], z0 = pa[r0*3+2];
        float x1 = pa[r1*3+0], y1 = pa[r1*3+1], z1 = pa[r1*3+2];
        nax2[i] = pack2(-x0, -x1);
        nay2[i] = pack2(-y0, -y1);
        naz2[i] = pack2(-z0, -z1);
        ha2[i]  = pack2(0.5f * (x0*x0 + y0*y0 + z0*z0),
                        0.5f * (x1*x1 + y1*y1 + z1*z1));
        rl[i] = INF; rh[i] = INF;
    }

    const int cbase = blockIdx.x * COLS_PER_BLOCK + warp * WC;

    // prefetch first tile's column
    int c = cbase + lane;
    float cx = pb[c*3+0], cy = pb[c*3+1], cz = pb[c*3+2];

    float csum = 0.0f;

#pragma unroll
    for (int t = 0; t < WC / 32; t++) {
        {   // stage duplicated packs: 32 B per column
            float hb = 0.5f * (cx*cx + cy*cy + cz*cz);
            ulonglong2 v0, v1;
            v0.x = pack2(cx, cx); v0.y = pack2(cy, cy);
            v1.x = pack2(cz, cz); v1.y = pack2(hb, hb);
            tile2[warp][lane][0] = v0;
            tile2[warp][lane][1] = v1;
        }
        __syncwarp();
        if (t + 1 < WC / 32) {               // prefetch next tile from gmem
            int cn = cbase + (t + 1) * 32 + lane;
            cx = pb[cn*3+0]; cy = pb[cn*3+1]; cz = pb[cn*3+2];
        }

        // systolic: at step j, lane l owns the accumulator for column (j+l)&31.
        // Column-min built in 4 independent chains to kill the serial FMNMX chain.
        float acc = INF;
#pragma unroll 2
        for (int j = 0; j < 32; j++) {
            int idx = (j + lane) & 31;
            ulonglong2 A  = tile2[warp][idx][0];
            ulonglong2 Bv = tile2[warp][idx][1];
            float c0 = INF, c1 = INF, c2 = INF, c3 = INF;
#pragma unroll
            for (int i = 0; i < 16; i += 4) {
                pair_step(nax2[i+0], nay2[i+0], naz2[i+0], ha2[i+0],
                          A.x, A.y, Bv.x, Bv.y, rl[i+0], rh[i+0], c0);
                pair_step(nax2[i+1], nay2[i+1], naz2[i+1], ha2[i+1],
                          A.x, A.y, Bv.x, Bv.y, rl[i+1], rh[i+1], c1);
                pair_step(nax2[i+2], nay2[i+2], naz2[i+2], ha2[i+2],
                          A.x, A.y, Bv.x, Bv.y, rl[i+2], rh[i+2], c2);
                pair_step(nax2[i+3], nay2[i+3], naz2[i+3], ha2[i+3],
                          A.x, A.y, Bv.x, Bv.y, rl[i+3], rh[i+3], c3);
            }
            acc = fminf(acc, fminf(fminf(c0, c1), fminf(c2, c3)));
            acc = __shfl_sync(0xffffffffu, acc, (lane + 1) & 31);
        }
        // lane l now holds the complete (1024-row) min of column l of this tile
        csum += acc;
        __syncwarp();
    }

    // per-warp sum of column mins -> one atomicAdd
#pragma unroll
    for (int o = 16; o > 0; o >>= 1)
        csum += __shfl_xor_sync(0xffffffffu, csum, o);
    if (lane == 0) atomicAdd(&g_acc[acc_idx], csum);

    // partial row-mins -> global (non-negative floats: int order preserved)
    int* rm = g_rowmin + rowoff;
#pragma unroll
    for (int i = 0; i < 16; i++) {
        int r0 = (2 * i) * 32 + lane;
        atomicMin(&rm[r0],      __float_as_int(rl[i]));
        atomicMin(&rm[r0 + 32], __float_as_int(rh[i]));
    }
}

// finalize: row-min sums (int4 loads) + consistency MSE + combine
__global__ __launch_bounds__(1024)
void k_final(const float* __restrict__ sp,
             const float* __restrict__ tsp,
             const float* __restrict__ M,
             float* __restrict__ out)
{
    int tid = threadIdx.x;

    // consistency: tmp[t,b,s,e] = sum_d sp[b,s,d]*M[t,d,e]; SSE vs tsp
    float e = 0.0f;
#pragma unroll
    for (int k = 0; k < 16; k++) {
        int idx = tid + k * 1024;          // [0, 16384) = T*B*S
        int t  = idx >> 13;
        int bs = idx & 8191;
        const float* p = sp + (size_t)bs * 3;
        float x = p[0], y = p[1], z = p[2];
        const float* m = M + t * 9;
        const float* q = tsp + (size_t)idx * 3;
#pragma unroll
        for (int cc = 0; cc < 3; cc++) {
            float v = fmaf(x, m[cc], fmaf(y, m[3 + cc], z * m[6 + cc]));
            float d = v - q[cc];
            e = fmaf(d, d, e);
        }
    }

    // row-min sums, vectorized: 24576 ints = 6144 int4 (first 2048 = chamfer1)
    const int4* rm4 = (const int4*)g_rowmin;
    float a1 = 0.0f, a2 = 0.0f;
#pragma unroll
    for (int k = 0; k < 6; k++) {
        int i = tid + k * 1024;
        int4 v = rm4[i];
        float s = __int_as_float(v.x) + __int_as_float(v.y)
                + __int_as_float(v.z) + __int_as_float(v.w);
        if (i < 2048) a1 += s; else a2 += s;
    }

    __shared__ float sh[1024];
    sh[tid] = a1; __syncthreads();
    for (int s = 512; s > 0; s >>= 1) { if (tid < s) sh[tid] += sh[tid + s]; __syncthreads(); }
    float rs1 = sh[0]; __syncthreads();
    sh[tid] = a2; __syncthreads();
    for (int s = 512; s > 0; s >>= 1) { if (tid < s) sh[tid] += sh[tid + s]; __syncthreads(); }
    float rs2 = sh[0]; __syncthreads();
    sh[tid] = e; __syncthreads();
    for (int s = 512; s > 0; s >>= 1) { if (tid < s) sh[tid] += sh[tid + s]; __syncthreads(); }

    if (tid == 0) {
        // t-space = dist/2; cd = mean_rowmin_t + mean_colmin_t
        float cd1 = rs1 / 8192.0f  + g_acc[0] / 131072.0f;   // 8*1024, 8*16384
        float cd2 = rs2 / 16384.0f + g_acc[1] / 262144.0f;   // 16*1024, 16*16384
        float consist = sh[0] * (1000.0f / 49152.0f);        // mean over T*B*S*D
        out[0] = (cd1 + cd2) / 3.0f + consist;               // /(T+1)
    }
}

extern "C" void kernel_launch(void* const* d_in, const int* in_sizes, int n_in,
                              void* d_out, int out_size) {
    const float* gt  = (const float*)d_in[0];   // [8,16384,3]
    const float* sp  = (const float*)d_in[1];   // [8,1024,3]
    const float* tgt = (const float*)d_in[2];   // [2,8,16384,3] -> 16 batches
    const float* tsp = (const float*)d_in[3];   // [2,8,1024,3]  -> 16 batches
    const float* M   = (const float*)d_in[4];   // [2,3,3]
    (void)in_sizes; (void)n_in; (void)out_size;

    k_init<<<24, 1024>>>();
    k_chamfer<<<dim3(NP / COLS_PER_BLOCK, 24), WARPS * 32>>>(sp, gt, tsp, tgt);
    k_final<<<1, 1024>>>(sp, tsp, M, (float*)d_out);
}

// round 10
// speedup vs baseline: 7.7902x; 1.3670x over previous
#include <cuda_runtime.h>
#include <cuda_fp16.h>

#define SD 1024          // structure points per batch (rows)
#define NP 16384         // gt points per batch (cols)
#define WC 64            // columns per warp
#define WARPS 4
#define COLS_PER_BLOCK (WARPS * WC)   // 256

// scratch (no allocations allowed)
__device__ __align__(16) int g_rowmin[24576]; // 8*1024 (cham1) + 16*1024 (cham2), float bits
__device__ float g_acc[4];                    // [0]=colsum1, [1]=colsum2

__device__ __forceinline__ unsigned h2u(__half2 h) {
    return *reinterpret_cast<unsigned*>(&h);
}
__device__ __forceinline__ __half2 u2h(unsigned u) {
    return *reinterpret_cast<__half2*>(&u);
}

__global__ __launch_bounds__(1024)
void k_init() {
    int i = blockIdx.x * 1024 + threadIdx.x;
    g_rowmin[i] = 0x7f800000;
    if (i < 4) g_acc[i] = 0.0f;
}

// merged chamfer: blockIdx.y in [0,24): y<16 -> (tsp,tgt) job, y>=16 -> (sp,gt) job
__global__ __launch_bounds__(WARPS * 32)
void k_chamfer(const float* __restrict__ sp,  const float* __restrict__ gt,
               const float* __restrict__ tsp, const float* __restrict__ tgt)
{
    __shared__ uint4 tile[WARPS][32];   // per column: {xx, yy, zz, hh} as half2 dups

    const int y    = blockIdx.y;
    const int tid  = threadIdx.x;
    const int lane = tid & 31;
    const int warp = tid >> 5;
    const __half2 HBIG = __float2half2_rn(60000.0f);

    const float* pa; const float* pb; int rowoff, acc_idx;
    if (y < 16) { pa = tsp + (size_t)y * SD * 3;       pb = tgt + (size_t)y * NP * 3;
                  rowoff = 8192 + y * SD;              acc_idx = 1; }
    else        { int b = y - 16;
                  pa = sp + (size_t)b * SD * 3;        pb = gt + (size_t)b * NP * 3;
                  rowoff = b * SD;                     acc_idx = 0; }

    // ---- all 1024 rows of this batch in this warp's registers (half2) ----
    // unit i packs rows (2i)*32+lane (lo half) and (2i+1)*32+lane (hi half)
    __half2 nax2[16], nay2[16], naz2[16], ha2[16], rl2[16];
#pragma unroll
    for (int i = 0; i < 16; i++) {
        int r0 = (2 * i) * 32 + lane;
        int r1 = r0 + 32;
        float x0 = pa[r0*3+0], y0 = pa[r0*3+1], z0 = pa[r0*3+2];
        float x1 = pa[r1*3+0], y1 = pa[r1*3+1], z1 = pa[r1*3+2];
        nax2[i] = __floats2half2_rn(-x0, -x1);
        nay2[i] = __floats2half2_rn(-y0, -y1);
        naz2[i] = __floats2half2_rn(-z0, -z1);
        ha2[i]  = __floats2half2_rn(0.5f * (x0*x0 + y0*y0 + z0*z0),
                                    0.5f * (x1*x1 + y1*y1 + z1*z1));
        rl2[i] = HBIG;
    }

    const int cbase = blockIdx.x * COLS_PER_BLOCK + warp * WC;

    // prefetch first tile's column
    int c = cbase + lane;
    float cx = pb[c*3+0], cy = pb[c*3+1], cz = pb[c*3+2];

    float csum = 0.0f;

#pragma unroll
    for (int t = 0; t < WC / 32; t++) {
        {   // stage: duplicated half2 packs, 16 B per column
            float hb = 0.5f * (cx*cx + cy*cy + cz*cz);
            uint4 v;
            v.x = h2u(__float2half2_rn(cx));
            v.y = h2u(__float2half2_rn(cy));
            v.z = h2u(__float2half2_rn(cz));
            v.w = h2u(__float2half2_rn(hb));
            tile[warp][lane] = v;
        }
        __syncwarp();
        if (t + 1 < WC / 32) {               // prefetch next tile from gmem
            int cn = cbase + (t + 1) * 32 + lane;
            cx = pb[cn*3+0]; cy = pb[cn*3+1]; cz = pb[cn*3+2];
        }

        // systolic: at step j, lane l owns the accumulator for column (j+l)&31.
        // t-surrogate q = ha + hb - dot(a,b)  (= dist^2/2), in half2 (2 rows/op).
        __half2 acc = HBIG;
#pragma unroll 2
        for (int j = 0; j < 32; j++) {
            int idx = (j + lane) & 31;
            uint4 P = tile[warp][idx];
            __half2 px2 = u2h(P.x), py2 = u2h(P.y), pz2 = u2h(P.z), hb2 = u2h(P.w);
            __half2 c0 = HBIG, c1 = HBIG, c2 = HBIG, c3 = HBIG;
#pragma unroll
            for (int i = 0; i < 16; i += 4) {
                __half2 q0 = __hadd2(__hfma2(nax2[i+0], px2,
                             __hfma2(nay2[i+0], py2,
                             __hfma2(naz2[i+0], pz2, ha2[i+0]))), hb2);
                rl2[i+0] = __hmin2(rl2[i+0], q0);  c0 = __hmin2(c0, q0);
                __half2 q1 = __hadd2(__hfma2(nax2[i+1], px2,
                             __hfma2(nay2[i+1], py2,
                             __hfma2(naz2[i+1], pz2, ha2[i+1]))), hb2);
                rl2[i+1] = __hmin2(rl2[i+1], q1);  c1 = __hmin2(c1, q1);
                __half2 q2 = __hadd2(__hfma2(nax2[i+2], px2,
                             __hfma2(nay2[i+2], py2,
                             __hfma2(naz2[i+2], pz2, ha2[i+2]))), hb2);
                rl2[i+2] = __hmin2(rl2[i+2], q2);  c2 = __hmin2(c2, q2);
                __half2 q3 = __hadd2(__hfma2(nax2[i+3], px2,
                             __hfma2(nay2[i+3], py2,
                             __hfma2(naz2[i+3], pz2, ha2[i+3]))), hb2);
                rl2[i+3] = __hmin2(rl2[i+3], q3);  c3 = __hmin2(c3, q3);
            }
            acc = __hmin2(acc, __hmin2(__hmin2(c0, c1), __hmin2(c2, c3)));
            acc = u2h(__shfl_sync(0xffffffffu, h2u(acc), (lane + 1) & 31));
        }
        // lane l: complete 1024-row min of column l of this tile (both halves)
        csum += fminf(__low2float(acc), __high2float(acc));
        __syncwarp();
    }

    // per-warp sum of column mins -> one atomicAdd
#pragma unroll
    for (int o = 16; o > 0; o >>= 1)
        csum += __shfl_xor_sync(0xffffffffu, csum, o);
    if (lane == 0) atomicAdd(&g_acc[acc_idx], csum);

    // partial row-mins -> global (values >= -2e-3 noise; int-min on float bits
    // errs only within fp16 noise near zero — inside the error budget)
    int* rm = g_rowmin + rowoff;
#pragma unroll
    for (int i = 0; i < 16; i++) {
        int r0 = (2 * i) * 32 + lane;
        atomicMin(&rm[r0],      __float_as_int(__low2float(rl2[i])));
        atomicMin(&rm[r0 + 32], __float_as_int(__high2float(rl2[i])));
    }
}

// finalize: row-min sums (int4 loads) + consistency MSE (fp32 exact) + combine
__global__ __launch_bounds__(1024)
void k_final(const float* __restrict__ sp,
             const float* __restrict__ tsp,
             const float* __restrict__ M,
             float* __restrict__ out)
{
    int tid = threadIdx.x;

    // consistency: tmp[t,b,s,e] = sum_d sp[b,s,d]*M[t,d,e]; SSE vs tsp
    float e = 0.0f;
#pragma unroll
    for (int k = 0; k < 16; k++) {
        int idx = tid + k * 1024;          // [0, 16384) = T*B*S
        int t  = idx >> 13;
        int bs = idx & 8191;
        const float* p = sp + (size_t)bs * 3;
        float x = p[0], y = p[1], z = p[2];
        const float* m = M + t * 9;
        const float* q = tsp + (size_t)idx * 3;
#pragma unroll
        for (int cc = 0; cc < 3; cc++) {
            float v = fmaf(x, m[cc], fmaf(y, m[3 + cc], z * m[6 + cc]));
            float d = v - q[cc];
            e = fmaf(d, d, e);
        }
    }

    // row-min sums, vectorized: 24576 ints = 6144 int4 (first 2048 = chamfer1)
    const int4* rm4 = (const int4*)g_rowmin;
    float a1 = 0.0f, a2 = 0.0f;
#pragma unroll
    for (int k = 0; k < 6; k++) {
        int i = tid + k * 1024;
        int4 v = rm4[i];
        float s = __int_as_float(v.x) + __int_as_float(v.y)
                + __int_as_float(v.z) + __int_as_float(v.w);
        if (i < 2048) a1 += s; else a2 += s;
    }

    __shared__ float sh[1024];
    sh[tid] = a1; __syncthreads();
    for (int s = 512; s > 0; s >>= 1) { if (tid < s) sh[tid] += sh[tid + s]; __syncthreads(); }
    float rs1 = sh[0]; __syncthreads();
    sh[tid] = a2; __syncthreads();
    for (int s = 512; s > 0; s >>= 1) { if (tid < s) sh[tid] += sh[tid + s]; __syncthreads(); }
    float rs2 = sh[0]; __syncthreads();
    sh[tid] = e; __syncthreads();
    for (int s = 512; s > 0; s >>= 1) { if (tid < s) sh[tid] += sh[tid + s]; __syncthreads(); }

    if (tid == 0) {
        // t-space = dist^2/2; cd = mean_rowmin_t + mean_colmin_t
        float cd1 = rs1 / 8192.0f  + g_acc[0] / 131072.0f;   // 8*1024, 8*16384
        float cd2 = rs2 / 16384.0f + g_acc[1] / 262144.0f;   // 16*1024, 16*16384
        float consist = sh[0] * (1000.0f / 49152.0f);        // mean over T*B*S*D
        out[0] = (cd1 + cd2) / 3.0f + consist;               // /(T+1)
    }
}

extern "C" void kernel_launch(void* const* d_in, const int* in_sizes, int n_in,
                              void* d_out, int out_size) {
    const float* gt  = (const float*)d_in[0];   // [8,16384,3]
    const float* sp  = (const float*)d_in[1];   // [8,1024,3]
    const float* tgt = (const float*)d_in[2];   // [2,8,16384,3] -> 16 batches
    const float* tsp = (const float*)d_in[3];   // [2,8,1024,3]  -> 16 batches
    const float* M   = (const float*)d_in[4];   // [2,3,3]
    (void)in_sizes; (void)n_in; (void)out_size;

    k_init<<<24, 1024>>>();
    k_chamfer<<<dim3(NP / COLS_PER_BLOCK, 24), WARPS * 32>>>(sp, gt, tsp, tgt);
    k_final<<<1, 1024>>>(sp, tsp, M, (float*)d_out);
}

// round 12
// speedup vs baseline: 7.8422x; 1.0067x over previous
#include <cuda_runtime.h>
#include <cuda_fp16.h>

#define SD 1024          // structure points per batch (rows)
#define NP 16384         // gt points per batch (cols)
#define WC 64            // columns per warp
#define WARPS 4
#define COLS_PER_BLOCK (WARPS * WC)   // 256

// scratch — ZERO-initialized at module load; k_final re-zeroes after each read,
// so every kernel_launch call (and every graph replay) starts from zeros.
// g_rowmin holds keys: key = 0x7f800000 - float_bits(q), q >= 0. key 0 == q = +inf.
__device__ __align__(16) int g_rowmin[24576]; // 8*1024 (cham1) + 16*1024 (cham2)
__device__ float g_acc[4];                    // [0]=colsum1, [1]=colsum2

__device__ __forceinline__ unsigned h2u(__half2 h) {
    return *reinterpret_cast<unsigned*>(&h);
}
__device__ __forceinline__ unsigned umin16x2(unsigned a, unsigned b) {
    unsigned d;
    asm("min.u16x2 %0, %1, %2;" : "=r"(d) : "r"(a), "r"(b));
    return d;
}
__device__ __forceinline__ float h_lo(unsigned v) {
    return __half2float(__ushort_as_half((unsigned short)(v & 0xffffu)));
}
__device__ __forceinline__ float h_hi(unsigned v) {
    return __half2float(__ushort_as_half((unsigned short)(v >> 16)));
}

// merged chamfer: blockIdx.y in [0,24): y<16 -> (tsp,tgt) job, y>=16 -> (sp,gt) job
__global__ __launch_bounds__(WARPS * 32)
void k_chamfer(const float* __restrict__ sp,  const float* __restrict__ gt,
               const float* __restrict__ tsp, const float* __restrict__ tgt)
{
    __shared__ uint4 tile[WARPS][32];   // per column: {xx, yy, zz, hh} as half2 dups

    const int y    = blockIdx.y;
    const int tid  = threadIdx.x;
    const int lane = tid & 31;
    const int warp = tid >> 5;
    const unsigned UBIG = 0x7bff7bffu;  // fp16 max in both halves

    const float* pa; const float* pb; int rowoff, acc_idx;
    if (y < 16) { pa = tsp + (size_t)y * SD * 3;       pb = tgt + (size_t)y * NP * 3;
                  rowoff = 8192 + y * SD;              acc_idx = 1; }
    else        { int b = y - 16;
                  pa = sp + (size_t)b * SD * 3;        pb = gt + (size_t)b * NP * 3;
                  rowoff = b * SD;                     acc_idx = 0; }

    // ---- all 1024 rows of this batch in this warp's registers (half2) ----
    // unit i packs rows (2i)*32+lane (lo half) and (2i+1)*32+lane (hi half)
    __half2 nax2[16], nay2[16], naz2[16], ha2[16];
    unsigned rl[16];
#pragma unroll
    for (int i = 0; i < 16; i++) {
        int r0 = (2 * i) * 32 + lane;
        int r1 = r0 + 32;
        float x0 = pa[r0*3+0], y0 = pa[r0*3+1], z0 = pa[r0*3+2];
        float x1 = pa[r1*3+0], y1 = pa[r1*3+1], z1 = pa[r1*3+2];
        nax2[i] = __floats2half2_rn(-x0, -x1);
        nay2[i] = __floats2half2_rn(-y0, -y1);
        naz2[i] = __floats2half2_rn(-z0, -z1);
        ha2[i]  = __floats2half2_rn(0.5f * (x0*x0 + y0*y0 + z0*z0),
                                    0.5f * (x1*x1 + y1*y1 + z1*z1));
        rl[i] = UBIG;
    }

    const int cbase = blockIdx.x * COLS_PER_BLOCK + warp * WC;

    // prefetch first tile's column
    int c = cbase + lane;
    float cx = pb[c*3+0], cy = pb[c*3+1], cz = pb[c*3+2];

    float csum = 0.0f;

#pragma unroll
    for (int t = 0; t < WC / 32; t++) {
        {   // stage: duplicated half2 packs, 16 B per column
            float hb = 0.5f * (cx*cx + cy*cy + cz*cz);
            uint4 v;
            v.x = h2u(__float2half2_rn(cx));
            v.y = h2u(__float2half2_rn(cy));
            v.z = h2u(__float2half2_rn(cz));
            v.w = h2u(__float2half2_rn(hb));
            tile[warp][lane] = v;
        }
        __syncwarp();
        if (t + 1 < WC / 32) {               // prefetch next tile from gmem
            int cn = cbase + (t + 1) * 32 + lane;
            cx = pb[cn*3+0]; cy = pb[cn*3+1]; cz = pb[cn*3+2];
        }

        // systolic: at step j, lane l owns the accumulator for column (j+l)&31.
        // q = ha + hb - dot(a,b) (= dist^2/2) in half2 (fma pipe);
        // mins as u16x2 integer min (alu pipe; valid for q >= 0, fp16-noise safe).
        unsigned acc = UBIG;
#pragma unroll 2
        for (int j = 0; j < 32; j++) {
            int idx = (j + lane) & 31;
            uint4 P = tile[warp][idx];
            __half2 px2 = *reinterpret_cast<__half2*>(&P.x);
            __half2 py2 = *reinterpret_cast<__half2*>(&P.y);
            __half2 pz2 = *reinterpret_cast<__half2*>(&P.z);
            __half2 hb2 = *reinterpret_cast<__half2*>(&P.w);
            unsigned c0 = UBIG, c1 = UBIG, c2 = UBIG, c3 = UBIG;
#pragma unroll
            for (int i = 0; i < 16; i += 4) {
                unsigned q0 = h2u(__hadd2(__hfma2(nax2[i+0], px2,
                              __hfma2(nay2[i+0], py2,
                              __hfma2(naz2[i+0], pz2, ha2[i+0]))), hb2));
                rl[i+0] = umin16x2(rl[i+0], q0);  c0 = umin16x2(c0, q0);
                unsigned q1 = h2u(__hadd2(__hfma2(nax2[i+1], px2,
                              __hfma2(nay2[i+1], py2,
                              __hfma2(naz2[i+1], pz2, ha2[i+1]))), hb2));
                rl[i+1] = umin16x2(rl[i+1], q1);  c1 = umin16x2(c1, q1);
                unsigned q2 = h2u(__hadd2(__hfma2(nax2[i+2], px2,
                              __hfma2(nay2[i+2], py2,
                              __hfma2(naz2[i+2], pz2, ha2[i+2]))), hb2));
                rl[i+2] = umin16x2(rl[i+2], q2);  c2 = umin16x2(c2, q2);
                unsigned q3 = h2u(__hadd2(__hfma2(nax2[i+3], px2,
                              __hfma2(nay2[i+3], py2,
                              __hfma2(naz2[i+3], pz2, ha2[i+3]))), hb2));
                rl[i+3] = umin16x2(rl[i+3], q3);  c3 = umin16x2(c3, q3);
            }
            acc = umin16x2(acc, umin16x2(umin16x2(c0, c1), umin16x2(c2, c3)));
            acc = __shfl_sync(0xffffffffu, acc, (lane + 1) & 31);
        }
        // lane l: complete 1024-row min of column l of this tile (both halves)
        csum += fminf(fmaxf(h_lo(acc), 0.0f), fmaxf(h_hi(acc), 0.0f));
        __syncwarp();
    }

    // per-warp sum of column mins -> one atomicAdd
#pragma unroll
    for (int o = 16; o > 0; o >>= 1)
        csum += __shfl_xor_sync(0xffffffffu, csum, o);
    if (lane == 0) atomicAdd(&g_acc[acc_idx], csum);

    // partial row-mins -> global as max-keys (zero-init friendly):
    // key = 0x7f800000 - float_bits(max(q,0));  atomicMax picks smallest q.
    int* rm = g_rowmin + rowoff;
#pragma unroll
    for (int i = 0; i < 16; i++) {
        int r0 = (2 * i) * 32 + lane;
        float q0 = fmaxf(h_lo(rl[i]), 0.0f);
        float q1 = fmaxf(h_hi(rl[i]), 0.0f);
        atomicMax(&rm[r0],      0x7f800000 - __float_as_int(q0));
        atomicMax(&rm[r0 + 32], 0x7f800000 - __float_as_int(q1));
    }
}

// finalize: row-min key sums + consistency MSE (fp32 exact) + combine + RESET state
__global__ __launch_bounds__(1024)
void k_final(const float* __restrict__ sp,
             const float* __restrict__ tsp,
             const float* __restrict__ M,
             float* __restrict__ out)
{
    int tid = threadIdx.x;

    // consistency: tmp[t,b,s,e] = sum_d sp[b,s,d]*M[t,d,e]; SSE vs tsp
    float e = 0.0f;
#pragma unroll
    for (int k = 0; k < 16; k++) {
        int idx = tid + k * 1024;          // [0, 16384) = T*B*S
        int t  = idx >> 13;
        int bs = idx & 8191;
        const float* p = sp + (size_t)bs * 3;
        float x = p[0], y = p[1], z = p[2];
        const float* m = M + t * 9;
        const float* q = tsp + (size_t)idx * 3;
#pragma unroll
        for (int cc = 0; cc < 3; cc++) {
            float v = fmaf(x, m[cc], fmaf(y, m[3 + cc], z * m[6 + cc]));
            float d = v - q[cc];
            e = fmaf(d, d, e);
        }
    }

    // row-min sums: decode keys, then zero the slots for the next call.
    int4* rm4 = (int4*)g_rowmin;
    const int4 Z = make_int4(0, 0, 0, 0);
    float a1 = 0.0f, a2 = 0.0f;
#pragma unroll
    for (int k = 0; k < 6; k++) {
        int i = tid + k * 1024;
        int4 v = rm4[i];
        float s = __int_as_float(0x7f800000 - v.x) + __int_as_float(0x7f800000 - v.y)
                + __int_as_float(0x7f800000 - v.z) + __int_as_float(0x7f800000 - v.w);
        rm4[i] = Z;                        // reset (each thread owns its slots)
        if (i < 2048) a1 += s; else a2 += s;
    }

    __shared__ float sh[1024];
    sh[tid] = a1; __syncthreads();
    for (int s = 512; s > 0; s >>= 1) { if (tid < s) sh[tid] += sh[tid + s]; __syncthreads(); }
    float rs1 = sh[0]; __syncthreads();
    sh[tid] = a2; __syncthreads();
    for (int s = 512; s > 0; s >>= 1) { if (tid < s) sh[tid] += sh[tid + s]; __syncthreads(); }
    float rs2 = sh[0]; __syncthreads();
    sh[tid] = e; __syncthreads();
    for (int s = 512; s > 0; s >>= 1) { if (tid < s) sh[tid] += sh[tid + s]; __syncthreads(); }

    if (tid == 0) {
        float a0c = g_acc[0], a1c = g_acc[1];
        // t-space = dist^2/2; cd = mean_rowmin_t + mean_colmin_t
        float cd1 = rs1 / 8192.0f  + a0c / 131072.0f;   // 8*1024, 8*16384
        float cd2 = rs2 / 16384.0f + a1c / 262144.0f;   // 16*1024, 16*16384
        float consist = sh[0] * (1000.0f / 49152.0f);   // mean over T*B*S*D
        out[0] = (cd1 + cd2) / 3.0f + consist;          // /(T+1)
        g_acc[0] = 0.0f; g_acc[1] = 0.0f;               // reset for next call
        g_acc[2] = 0.0f; g_acc[3] = 0.0f;
    }
}

extern "C" void kernel_launch(void* const* d_in, const int* in_sizes, int n_in,
                              void* d_out, int out_size) {
    const float* gt  = (const float*)d_in[0];   // [8,16384,3]
    const float* sp  = (const float*)d_in[1];   // [8,1024,3]
    const float* tgt = (const float*)d_in[2];   // [2,8,16384,3] -> 16 batches
    const float* tsp = (const float*)d_in[3];   // [2,8,1024,3]  -> 16 batches
    const float* M   = (const float*)d_in[4];   // [2,3,3]
    (void)in_sizes; (void)n_in; (void)out_size;

    k_chamfer<<<dim3(NP / COLS_PER_BLOCK, 24), WARPS * 32>>>(sp, gt, tsp, tgt);
    k_final<<<1, 1024>>>(sp, tsp, M, (float*)d_out);
}

// round 13
// speedup vs baseline: 8.0978x; 1.0326x over previous
#include <cuda_runtime.h>
#include <cuda_fp16.h>

#define SD 1024          // structure points per batch (rows)
#define NP 16384         // gt points per batch (cols)
#define WC 64            // columns per warp
#define WARPS 4
#define COLS_PER_BLOCK (WARPS * WC)   // 256

// scratch — ZERO-initialized at module load; reset inline after each read,
// so every kernel_launch call (and every graph replay) starts from zeros.
// g_rowmin holds keys: key = 0x7f800000 - float_bits(q), q >= 0. key 0 == q = +inf.
__device__ __align__(16) int g_rowmin[24576]; // 8*1024 (cham1) + 16*1024 (cham2)
__device__ float g_acc[8];  // [0]=colsum1 [1]=colsum2 [2]=mse [4]=rowsum1 [5]=rowsum2

__device__ __forceinline__ unsigned h2u(__half2 h) {
    return *reinterpret_cast<unsigned*>(&h);
}
__device__ __forceinline__ unsigned umin16x2(unsigned a, unsigned b) {
    unsigned d;
    asm("min.u16x2 %0, %1, %2;" : "=r"(d) : "r"(a), "r"(b));
    return d;
}
__device__ __forceinline__ float h_lo(unsigned v) {
    return __half2float(__ushort_as_half((unsigned short)(v & 0xffffu)));
}
__device__ __forceinline__ float h_hi(unsigned v) {
    return __half2float(__ushort_as_half((unsigned short)(v >> 16)));
}

// merged chamfer: blockIdx.y in [0,24): y<16 -> (tsp,tgt) job, y>=16 -> (sp,gt) job
__global__ __launch_bounds__(WARPS * 32)
void k_chamfer(const float* __restrict__ sp,  const float* __restrict__ gt,
               const float* __restrict__ tsp, const float* __restrict__ tgt)
{
    __shared__ uint4 tile[WARPS][32];   // per column: {xx, yy, zz, hh} as half2 dups

    const int y    = blockIdx.y;
    const int tid  = threadIdx.x;
    const int lane = tid & 31;
    const int warp = tid >> 5;
    const unsigned UBIG = 0x7bff7bffu;  // fp16 max in both halves

    const float* pa; const float* pb; int rowoff, acc_idx;
    if (y < 16) { pa = tsp + (size_t)y * SD * 3;       pb = tgt + (size_t)y * NP * 3;
                  rowoff = 8192 + y * SD;              acc_idx = 1; }
    else        { int b = y - 16;
                  pa = sp + (size_t)b * SD * 3;        pb = gt + (size_t)b * NP * 3;
                  rowoff = b * SD;                     acc_idx = 0; }

    // ---- all 1024 rows of this batch in this warp's registers (half2) ----
    // unit i packs rows (2i)*32+lane (lo half) and (2i+1)*32+lane (hi half)
    __half2 nax2[16], nay2[16], naz2[16], ha2[16];
    unsigned rl[16];
#pragma unroll
    for (int i = 0; i < 16; i++) {
        int r0 = (2 * i) * 32 + lane;
        int r1 = r0 + 32;
        float x0 = pa[r0*3+0], y0 = pa[r0*3+1], z0 = pa[r0*3+2];
        float x1 = pa[r1*3+0], y1 = pa[r1*3+1], z1 = pa[r1*3+2];
        nax2[i] = __floats2half2_rn(-x0, -x1);
        nay2[i] = __floats2half2_rn(-y0, -y1);
        naz2[i] = __floats2half2_rn(-z0, -z1);
        ha2[i]  = __floats2half2_rn(0.5f * (x0*x0 + y0*y0 + z0*z0),
                                    0.5f * (x1*x1 + y1*y1 + z1*z1));
        rl[i] = UBIG;
    }

    const int cbase = blockIdx.x * COLS_PER_BLOCK + warp * WC;

    // prefetch first tile's column
    int c = cbase + lane;
    float cx = pb[c*3+0], cy = pb[c*3+1], cz = pb[c*3+2];

    float csum = 0.0f;

#pragma unroll
    for (int t = 0; t < WC / 32; t++) {
        {   // stage: duplicated half2 packs, 16 B per column
            float hb = 0.5f * (cx*cx + cy*cy + cz*cz);
            uint4 v;
            v.x = h2u(__float2half2_rn(cx));
            v.y = h2u(__float2half2_rn(cy));
            v.z = h2u(__float2half2_rn(cz));
            v.w = h2u(__float2half2_rn(hb));
            tile[warp][lane] = v;
        }
        __syncwarp();
        if (t + 1 < WC / 32) {               // prefetch next tile from gmem
            int cn = cbase + (t + 1) * 32 + lane;
            cx = pb[cn*3+0]; cy = pb[cn*3+1]; cz = pb[cn*3+2];
        }

        // systolic: at step j, lane l owns the accumulator for column (j+l)&31.
        // q = ha + hb - dot(a,b) (= dist^2/2) in half2 (fma pipe);
        // mins as u16x2 integer min (valid for q >= 0, fp16-noise safe).
        unsigned acc = UBIG;
#pragma unroll 2
        for (int j = 0; j < 32; j++) {
            int idx = (j + lane) & 31;
            uint4 P = tile[warp][idx];
            __half2 px2 = *reinterpret_cast<__half2*>(&P.x);
            __half2 py2 = *reinterpret_cast<__half2*>(&P.y);
            __half2 pz2 = *reinterpret_cast<__half2*>(&P.z);
            __half2 hb2 = *reinterpret_cast<__half2*>(&P.w);
            unsigned c0 = UBIG, c1 = UBIG, c2 = UBIG, c3 = UBIG;
#pragma unroll
            for (int i = 0; i < 16; i += 4) {
                unsigned q0 = h2u(__hadd2(__hfma2(nax2[i+0], px2,
                              __hfma2(nay2[i+0], py2,
                              __hfma2(naz2[i+0], pz2, ha2[i+0]))), hb2));
                rl[i+0] = umin16x2(rl[i+0], q0);  c0 = umin16x2(c0, q0);
                unsigned q1 = h2u(__hadd2(__hfma2(nax2[i+1], px2,
                              __hfma2(nay2[i+1], py2,
                              __hfma2(naz2[i+1], pz2, ha2[i+1]))), hb2));
                rl[i+1] = umin16x2(rl[i+1], q1);  c1 = umin16x2(c1, q1);
                unsigned q2 = h2u(__hadd2(__hfma2(nax2[i+2], px2,
                              __hfma2(nay2[i+2], py2,
                              __hfma2(naz2[i+2], pz2, ha2[i+2]))), hb2));
                rl[i+2] = umin16x2(rl[i+2], q2);  c2 = umin16x2(c2, q2);
                unsigned q3 = h2u(__hadd2(__hfma2(nax2[i+3], px2,
                              __hfma2(nay2[i+3], py2,
                              __hfma2(naz2[i+3], pz2, ha2[i+3]))), hb2));
                rl[i+3] = umin16x2(rl[i+3], q3);  c3 = umin16x2(c3, q3);
            }
            acc = umin16x2(acc, umin16x2(umin16x2(c0, c1), umin16x2(c2, c3)));
            acc = __shfl_sync(0xffffffffu, acc, (lane + 1) & 31);
        }
        // lane l: complete 1024-row min of column l of this tile (both halves)
        csum += fminf(fmaxf(h_lo(acc), 0.0f), fmaxf(h_hi(acc), 0.0f));
        __syncwarp();
    }

    // per-warp sum of column mins -> one atomicAdd
#pragma unroll
    for (int o = 16; o > 0; o >>= 1)
        csum += __shfl_xor_sync(0xffffffffu, csum, o);
    if (lane == 0) atomicAdd(&g_acc[acc_idx], csum);

    // partial row-mins -> global as max-keys (zero-init friendly):
    // key = 0x7f800000 - float_bits(max(q,0));  atomicMax picks smallest q.
    int* rm = g_rowmin + rowoff;
#pragma unroll
    for (int i = 0; i < 16; i++) {
        int r0 = (2 * i) * 32 + lane;
        float q0 = fmaxf(h_lo(rl[i]), 0.0f);
        float q1 = fmaxf(h_hi(rl[i]), 0.0f);
        atomicMax(&rm[r0],      0x7f800000 - __float_as_int(q0));
        atomicMax(&rm[r0 + 32], 0x7f800000 - __float_as_int(q1));
    }
}

// parallel reduction: consistency MSE + row-min key sums; resets row-min slots.
__global__ __launch_bounds__(256)
void k_red(const float* __restrict__ sp,
           const float* __restrict__ tsp,
           const float* __restrict__ M)
{
    const int gid = blockIdx.x * 256 + threadIdx.x;   // 48*256 = 12288 threads
    const int lane = threadIdx.x & 31;

    // consistency: tmp[t,b,s,e] = sum_d sp[b,s,d]*M[t,d,e]; SSE vs tsp
    float e = 0.0f;
    for (int idx = gid; idx < 16384; idx += 12288) {
        int t  = idx >> 13;
        int bs = idx & 8191;
        const float* p = sp + (size_t)bs * 3;
        float x = p[0], y = p[1], z = p[2];
        const float* m = M + t * 9;
        const float* q = tsp + (size_t)idx * 3;
#pragma unroll
        for (int cc = 0; cc < 3; cc++) {
            float v = fmaf(x, m[cc], fmaf(y, m[3 + cc], z * m[6 + cc]));
            float d = v - q[cc];
            e = fmaf(d, d, e);
        }
    }

    // row-min key sums: 6144 int4 (first 2048 = chamfer1); reset after read.
    int4* rm4 = (int4*)g_rowmin;
    float a1 = 0.0f, a2 = 0.0f;
    for (int i = gid; i < 6144; i += 12288) {
        int4 v = rm4[i];
        float s = __int_as_float(0x7f800000 - v.x) + __int_as_float(0x7f800000 - v.y)
                + __int_as_float(0x7f800000 - v.z) + __int_as_float(0x7f800000 - v.w);
        rm4[i] = make_int4(0, 0, 0, 0);
        if (i < 2048) a1 += s; else a2 += s;
    }

    // warp reduce + one atomicAdd per warp per accumulator
#pragma unroll
    for (int o = 16; o > 0; o >>= 1) {
        e  += __shfl_xor_sync(0xffffffffu, e,  o);
        a1 += __shfl_xor_sync(0xffffffffu, a1, o);
        a2 += __shfl_xor_sync(0xffffffffu, a2, o);
    }
    if (lane == 0) {
        atomicAdd(&g_acc[2], e);
        atomicAdd(&g_acc[4], a1);
        atomicAdd(&g_acc[5], a2);
    }
}

// combine + reset accumulators
__global__ __launch_bounds__(32)
void k_out(float* __restrict__ out)
{
    if (threadIdx.x == 0) {
        float cs1 = g_acc[0], cs2 = g_acc[1], mse = g_acc[2];
        float rs1 = g_acc[4], rs2 = g_acc[5];
        // t-space = dist^2/2; cd = mean_rowmin_t + mean_colmin_t
        float cd1 = rs1 / 8192.0f  + cs1 / 131072.0f;   // 8*1024, 8*16384
        float cd2 = rs2 / 16384.0f + cs2 / 262144.0f;   // 16*1024, 16*16384
        float consist = mse * (1000.0f / 49152.0f);     // mean over T*B*S*D
        out[0] = (cd1 + cd2) / 3.0f + consist;          // /(T+1)
#pragma unroll
        for (int i = 0; i < 8; i++) g_acc[i] = 0.0f;    // reset for next call
    }
}

extern "C" void kernel_launch(void* const* d_in, const int* in_sizes, int n_in,
                              void* d_out, int out_size) {
    const float* gt  = (const float*)d_in[0];   // [8,16384,3]
    const float* sp  = (const float*)d_in[1];   // [8,1024,3]
    const float* tgt = (const float*)d_in[2];   // [2,8,16384,3] -> 16 batches
    const float* tsp = (const float*)d_in[3];   // [2,8,1024,3]  -> 16 batches
    const float* M   = (const float*)d_in[4];   // [2,3,3]
    (void)in_sizes; (void)n_in; (void)out_size;

    k_chamfer<<<dim3(NP / COLS_PER_BLOCK, 24), WARPS * 32>>>(sp, gt, tsp, tgt);
    k_red<<<48, 256>>>(sp, tsp, M);
    k_out<<<1, 32>>>((float*)d_out);
}

// round 14
// speedup vs baseline: 8.2881x; 1.0235x over previous
#include <cuda_runtime.h>
#include <cuda_fp16.h>

#define SD 1024          // structure points per batch (rows)
#define NP 16384         // gt points per batch (cols)
#define WC 64            // columns per warp per chunk
#define WARPS 4
#define COLS_PER_BLOCK (WARPS * WC)   // 256
#define XGRP 24          // x-groups per batch; 576 blocks total = single wave

// scratch — ZERO-initialized at module load; reset inline after each read,
// so every kernel_launch call (and every graph replay) starts from zeros.
// g_rowmin holds keys: key = 0x7f800000 - float_bits(q), q >= 0. key 0 == q = +inf.
__device__ __align__(16) int g_rowmin[24576]; // 8*1024 (cham1) + 16*1024 (cham2)
__device__ float g_acc[8];  // [0]=colsum1 [1]=colsum2 [2]=mse [4]=rowsum1 [5]=rowsum2

__device__ __forceinline__ unsigned h2u(__half2 h) {
    return *reinterpret_cast<unsigned*>(&h);
}
__device__ __forceinline__ unsigned umin16x2(unsigned a, unsigned b) {
    unsigned d;
    asm("min.u16x2 %0, %1, %2;" : "=r"(d) : "r"(a), "r"(b));
    return d;
}
__device__ __forceinline__ float h_lo(unsigned v) {
    return __half2float(__ushort_as_half((unsigned short)(v & 0xffffu)));
}
__device__ __forceinline__ float h_hi(unsigned v) {
    return __half2float(__ushort_as_half((unsigned short)(v >> 16)));
}

// merged chamfer, single wave: blockIdx.y in [0,24) selects job;
// blockIdx.x = j in [0,24) processes column-chunks {j, j+24, j+48} (each 256 cols).
__global__ __launch_bounds__(WARPS * 32)
void k_chamfer(const float* __restrict__ sp,  const float* __restrict__ gt,
               const float* __restrict__ tsp, const float* __restrict__ tgt)
{
    __shared__ uint4 tile[WARPS][32];   // per column: {xx, yy, zz, hh} as half2 dups

    const int y    = blockIdx.y;
    const int jg   = blockIdx.x;        // x-group
    const int tid  = threadIdx.x;
    const int lane = tid & 31;
    const int warp = tid >> 5;
    const unsigned UBIG = 0x7bff7bffu;  // fp16 max in both halves

    const float* pa; const float* pb; int rowoff, acc_idx;
    if (y < 16) { pa = tsp + (size_t)y * SD * 3;       pb = tgt + (size_t)y * NP * 3;
                  rowoff = 8192 + y * SD;              acc_idx = 1; }
    else        { int b = y - 16;
                  pa = sp + (size_t)b * SD * 3;        pb = gt + (size_t)b * NP * 3;
                  rowoff = b * SD;                     acc_idx = 0; }

    // ---- all 1024 rows of this batch in this warp's registers (half2) ----
    // unit i packs rows (2i)*32+lane (lo half) and (2i+1)*32+lane (hi half)
    __half2 nax2[16], nay2[16], naz2[16], ha2[16];
    unsigned rl[16];
#pragma unroll
    for (int i = 0; i < 16; i++) {
        int r0 = (2 * i) * 32 + lane;
        int r1 = r0 + 32;
        float x0 = pa[r0*3+0], y0 = pa[r0*3+1], z0 = pa[r0*3+2];
        float x1 = pa[r1*3+0], y1 = pa[r1*3+1], z1 = pa[r1*3+2];
        nax2[i] = __floats2half2_rn(-x0, -x1);
        nay2[i] = __floats2half2_rn(-y0, -y1);
        naz2[i] = __floats2half2_rn(-z0, -z1);
        ha2[i]  = __floats2half2_rn(0.5f * (x0*x0 + y0*y0 + z0*z0),
                                    0.5f * (x1*x1 + y1*y1 + z1*z1));
        rl[i] = UBIG;
    }

    float csum = 0.0f;
    const int nchunks = (jg < 16) ? 3 : 2;   // chunks jg, jg+24, jg+48 (<64)

    for (int k = 0; k < nchunks; k++) {
        const int cbase = (jg + 24 * k) * COLS_PER_BLOCK + warp * WC;

        // prefetch first tile's column of this chunk
        int c = cbase + lane;
        float cx = pb[c*3+0], cy = pb[c*3+1], cz = pb[c*3+2];

#pragma unroll
        for (int t = 0; t < WC / 32; t++) {
            {   // stage: duplicated half2 packs, 16 B per column
                float hb = 0.5f * (cx*cx + cy*cy + cz*cz);
                uint4 v;
                v.x = h2u(__float2half2_rn(cx));
                v.y = h2u(__float2half2_rn(cy));
                v.z = h2u(__float2half2_rn(cz));
                v.w = h2u(__float2half2_rn(hb));
                tile[warp][lane] = v;
            }
            __syncwarp();
            if (t + 1 < WC / 32) {           // prefetch next tile from gmem
                int cn = cbase + (t + 1) * 32 + lane;
                cx = pb[cn*3+0]; cy = pb[cn*3+1]; cz = pb[cn*3+2];
            }

            // systolic: at step j, lane l owns the accumulator for column (j+l)&31.
            // q = ha + hb - dot(a,b) (= dist^2/2) in half2 (fma pipe);
            // mins as u16x2 integer min (valid for q >= 0, fp16-noise safe).
            unsigned acc = UBIG;
#pragma unroll 2
            for (int j = 0; j < 32; j++) {
                int idx = (j + lane) & 31;
                uint4 P = tile[warp][idx];
                __half2 px2 = *reinterpret_cast<__half2*>(&P.x);
                __half2 py2 = *reinterpret_cast<__half2*>(&P.y);
                __half2 pz2 = *reinterpret_cast<__half2*>(&P.z);
                __half2 hb2 = *reinterpret_cast<__half2*>(&P.w);
                unsigned c0 = UBIG, c1 = UBIG, c2 = UBIG, c3 = UBIG;
#pragma unroll
                for (int i = 0; i < 16; i += 4) {
                    unsigned q0 = h2u(__hadd2(__hfma2(nax2[i+0], px2,
                                  __hfma2(nay2[i+0], py2,
                                  __hfma2(naz2[i+0], pz2, ha2[i+0]))), hb2));
                    rl[i+0] = umin16x2(rl[i+0], q0);  c0 = umin16x2(c0, q0);
                    unsigned q1 = h2u(__hadd2(__hfma2(nax2[i+1], px2,
                                  __hfma2(nay2[i+1], py2,
                                  __hfma2(naz2[i+1], pz2, ha2[i+1]))), hb2));
                    rl[i+1] = umin16x2(rl[i+1], q1);  c1 = umin16x2(c1, q1);
                    unsigned q2 = h2u(__hadd2(__hfma2(nax2[i+2], px2,
                                  __hfma2(nay2[i+2], py2,
                                  __hfma2(naz2[i+2], pz2, ha2[i+2]))), hb2));
                    rl[i+2] = umin16x2(rl[i+2], q2);  c2 = umin16x2(c2, q2);
                    unsigned q3 = h2u(__hadd2(__hfma2(nax2[i+3], px2,
                                  __hfma2(nay2[i+3], py2,
                                  __hfma2(naz2[i+3], pz2, ha2[i+3]))), hb2));
                    rl[i+3] = umin16x2(rl[i+3], q3);  c3 = umin16x2(c3, q3);
                }
                acc = umin16x2(acc, umin16x2(umin16x2(c0, c1), umin16x2(c2, c3)));
                acc = __shfl_sync(0xffffffffu, acc, (lane + 1) & 31);
            }
            // lane l: complete 1024-row min of column l of this tile (both halves)
            csum += fminf(fmaxf(h_lo(acc), 0.0f), fmaxf(h_hi(acc), 0.0f));
            __syncwarp();
        }
    }

    // per-warp sum of column mins -> one atomicAdd
#pragma unroll
    for (int o = 16; o > 0; o >>= 1)
        csum += __shfl_xor_sync(0xffffffffu, csum, o);
    if (lane == 0) atomicAdd(&g_acc[acc_idx], csum);

    // partial row-mins -> global as max-keys (zero-init friendly):
    // key = 0x7f800000 - float_bits(max(q,0));  atomicMax picks smallest q.
    int* rm = g_rowmin + rowoff;
#pragma unroll
    for (int i = 0; i < 16; i++) {
        int r0 = (2 * i) * 32 + lane;
        float q0 = fmaxf(h_lo(rl[i]), 0.0f);
        float q1 = fmaxf(h_hi(rl[i]), 0.0f);
        atomicMax(&rm[r0],      0x7f800000 - __float_as_int(q0));
        atomicMax(&rm[r0 + 32], 0x7f800000 - __float_as_int(q1));
    }
}

// parallel reduction: consistency MSE + row-min key sums; resets row-min slots.
__global__ __launch_bounds__(256)
void k_red(const float* __restrict__ sp,
           const float* __restrict__ tsp,
           const float* __restrict__ M)
{
    const int gid = blockIdx.x * 256 + threadIdx.x;   // 48*256 = 12288 threads
    const int lane = threadIdx.x & 31;

    // consistency: tmp[t,b,s,e] = sum_d sp[b,s,d]*M[t,d,e]; SSE vs tsp
    float e = 0.0f;
    for (int idx = gid; idx < 16384; idx += 12288) {
        int t  = idx >> 13;
        int bs = idx & 8191;
        const float* p = sp + (size_t)bs * 3;
        float x = p[0], y = p[1], z = p[2];
        const float* m = M + t * 9;
        const float* q = tsp + (size_t)idx * 3;
#pragma unroll
        for (int cc = 0; cc < 3; cc++) {
            float v = fmaf(x, m[cc], fmaf(y, m[3 + cc], z * m[6 + cc]));
            float d = v - q[cc];
            e = fmaf(d, d, e);
        }
    }

    // row-min key sums: 6144 int4 (first 2048 = chamfer1); reset after read.
    int4* rm4 = (int4*)g_rowmin;
    float a1 = 0.0f, a2 = 0.0f;
    for (int i = gid; i < 6144; i += 12288) {
        int4 v = rm4[i];
        float s = __int_as_float(0x7f800000 - v.x) + __int_as_float(0x7f800000 - v.y)
                + __int_as_float(0x7f800000 - v.z) + __int_as_float(0x7f800000 - v.w);
        rm4[i] = make_int4(0, 0, 0, 0);
        if (i < 2048) a1 += s; else a2 += s;
    }

    // warp reduce + one atomicAdd per warp per accumulator
#pragma unroll
    for (int o = 16; o > 0; o >>= 1) {
        e  += __shfl_xor_sync(0xffffffffu, e,  o);
        a1 += __shfl_xor_sync(0xffffffffu, a1, o);
        a2 += __shfl_xor_sync(0xffffffffu, a2, o);
    }
    if (lane == 0) {
        atomicAdd(&g_acc[2], e);
        atomicAdd(&g_acc[4], a1);
        atomicAdd(&g_acc[5], a2);
    }
}

// combine + reset accumulators
__global__ __launch_bounds__(32)
void k_out(float* __restrict__ out)
{
    if (threadIdx.x == 0) {
        float cs1 = g_acc[0], cs2 = g_acc[1], mse = g_acc[2];
        float rs1 = g_acc[4], rs2 = g_acc[5];
        // t-space = dist^2/2; cd = mean_rowmin_t + mean_colmin_t
        float cd1 = rs1 / 8192.0f  + cs1 / 131072.0f;   // 8*1024, 8*16384
        float cd2 = rs2 / 16384.0f + cs2 / 262144.0f;   // 16*1024, 16*16384
        float consist = mse * (1000.0f / 49152.0f);     // mean over T*B*S*D
        out[0] = (cd1 + cd2) / 3.0f + consist;          // /(T+1)
#pragma unroll
        for (int i = 0; i < 8; i++) g_acc[i] = 0.0f;    // reset for next call
    }
}

extern "C" void kernel_launch(void* const* d_in, const int* in_sizes, int n_in,
                              void* d_out, int out_size) {
    const float* gt  = (const float*)d_in[0];   // [8,16384,3]
    const float* sp  = (const float*)d_in[1];   // [8,1024,3]
    const float* tgt = (const float*)d_in[2];   // [2,8,16384,3] -> 16 batches
    const float* tsp = (const float*)d_in[3];   // [2,8,1024,3]  -> 16 batches
    const float* M   = (const float*)d_in[4];   // [2,3,3]
    (void)in_sizes; (void)n_in; (void)out_size;

    k_chamfer<<<dim3(XGRP, 24), WARPS * 32>>>(sp, gt, tsp, tgt);
    k_red<<<48, 256>>>(sp, tsp, M);
    k_out<<<1, 32>>>((float*)d_out);
}